// round 14
// baseline (speedup 1.0000x reference)
#include <cuda_runtime.h>
#include <cuda_fp16.h>
#include <cstdint>

#define NB     64
#define EMB    512
#define HID    1024
#define LSEQ   512
#define TSTEPS 511

// -------- device global scratch (allocation-free rule) --------
__device__ __align__(16) __half g_X[(size_t)TSTEPS * NB * EMB]; // [t][n][k] 33.5 MB
__device__ __align__(16) __half g_B0[3072 * 1536];              // row j: [Wih0 | Whh0]
__device__ __align__(16) __half g_B1[3072 * 2048];              // row j: [Wih1 | Whh1]
__device__ __align__(16) float  g_h0f[2][NB * HID];
__device__ __align__(16) float  g_h1f[2][NB * HID];
__device__ __align__(16) __half g_h0h[2][NB * HID];
__device__ __align__(16) __half g_h1h[2][NB * HID];

// -------- PTX helpers --------
__device__ __forceinline__ void cp_async16(void* s, const void* g) {
    uint32_t sa = (uint32_t)__cvta_generic_to_shared(s);
    asm volatile("cp.async.cg.shared.global [%0], [%1], 16;\n" :: "r"(sa), "l"(g));
}
__device__ __forceinline__ void ldsm4(uint32_t& r0, uint32_t& r1, uint32_t& r2, uint32_t& r3,
                                      const void* p) {
    uint32_t a = (uint32_t)__cvta_generic_to_shared(p);
    asm volatile("ldmatrix.sync.aligned.m8n8.x4.shared.b16 {%0,%1,%2,%3}, [%4];\n"
                 : "=r"(r0), "=r"(r1), "=r"(r2), "=r"(r3) : "r"(a));
}
__device__ __forceinline__ void mma_fp16(float (&d)[4], uint32_t a0, uint32_t a1, uint32_t a2,
                                         uint32_t a3, uint32_t b0, uint32_t b1) {
    asm volatile(
        "mma.sync.aligned.m16n8k16.row.col.f32.f16.f16.f32 "
        "{%0,%1,%2,%3},{%4,%5,%6,%7},{%8,%9},{%0,%1,%2,%3};\n"
        : "+f"(d[0]), "+f"(d[1]), "+f"(d[2]), "+f"(d[3])
        : "r"(a0), "r"(a1), "r"(a2), "r"(a3), "r"(b0), "r"(b1));
}

// -------- one-time (per replay) prep kernels --------
__global__ void k_init(const float* __restrict__ dec_init) {
    for (int i = blockIdx.x * blockDim.x + threadIdx.x; i < NB * HID;
         i += gridDim.x * blockDim.x) {
        float v0 = dec_init[i];
        float v1 = dec_init[NB * HID + i];
        g_h0f[0][i] = v0; g_h0h[0][i] = __float2half(v0);
        g_h1f[0][i] = v1; g_h1h[0][i] = __float2half(v1);
    }
}

__global__ void k_pack(const float* __restrict__ Wih0, const float* __restrict__ Whh0,
                       const float* __restrict__ Wih1, const float* __restrict__ Whh1) {
    const int N0 = 3072 * 1536;
    const int N1 = 3072 * 2048;
    for (int i = blockIdx.x * blockDim.x + threadIdx.x; i < N0 + N1;
         i += gridDim.x * blockDim.x) {
        if (i < N0) {
            int j = i / 1536, k = i % 1536;
            float v = (k < 512) ? Wih0[(size_t)j * 512 + k] : Whh0[(size_t)j * 1024 + (k - 512)];
            g_B0[i] = __float2half(v);
        } else {
            int ii = i - N0;
            int j = ii >> 11, k = ii & 2047;
            float v = (k < 1024) ? Wih1[(size_t)j * 1024 + k] : Whh1[(size_t)j * 1024 + (k - 1024)];
            g_B1[ii] = __float2half(v);
        }
    }
}

__global__ void k_embed(const int* __restrict__ tokens, const float* __restrict__ emb) {
    int tn = blockIdx.x;          // t*64 + n
    int t = tn >> 6, n = tn & 63;
    int tok = tokens[n * LSEQ + t];      // tokens[:, :-1] -> col t < 511
    const float* src = emb + (size_t)tok * EMB;
    __half* dst = g_X + (size_t)tn * EMB;
    for (int k = threadIdx.x; k < EMB; k += blockDim.x)
        dst[k] = __float2half(src[k]);
}

__global__ void k_final(float* __restrict__ out) {
    size_t base = (size_t)NB * TSTEPS * HID;
    for (int i = blockIdx.x * blockDim.x + threadIdx.x; i < NB * HID;
         i += gridDim.x * blockDim.x) {
        out[base + i] = g_h0f[1][i];                // 511 steps -> final parity buffer = 1
        out[base + NB * HID + i] = g_h1f[1][i];
    }
}

// -------- fused GEMM + GRU gate body (one layer, one step, one 16-unit tile) --------
// 128 threads (4 warps = 4 m16 batch tiles). GEMM: M=64, N=48 (3 gates x 16 units),
// K = kA0 + 1024 fused: accA accumulates the input part (gi), accB the hidden part (gh),
// split at the K boundary, because n = tanh(gi_n + r * gh_n).
__device__ __forceinline__ void step_body(int layer, int t, int jblk,
                                          const float* __restrict__ b_ih,
                                          const float* __restrict__ b_hh,
                                          float* __restrict__ out,
                                          unsigned char* smraw) {
    const int tid = threadIdx.x;
    const int wid = tid >> 5;
    const int lane = tid & 31;
    const int j0 = jblk * 16;
    const int p = t & 1;

    const __half *A0, *A1, *Bm;
    const float* h_old;
    float* hnf;
    __half* hnh;
    float* hids;
    int sA0, kA0, sA1, Kdim;
    if (layer == 0) {
        A0 = g_X + (size_t)t * NB * EMB; sA0 = EMB; kA0 = EMB;
        A1 = g_h0h[p]; sA1 = HID;
        Bm = g_B0; Kdim = 1536;
        h_old = g_h0f[p]; hnf = g_h0f[p ^ 1]; hnh = g_h0h[p ^ 1]; hids = nullptr;
    } else {
        A0 = g_h0h[p ^ 1]; sA0 = HID; kA0 = HID;
        A1 = g_h1h[p]; sA1 = HID;
        Bm = g_B1; Kdim = 2048;
        h_old = g_h1f[p]; hnf = g_h1f[p ^ 1]; hnh = g_h1h[p ^ 1];
        hids = out + (size_t)t * HID;
    }
    const int NC = Kdim >> 6;     // K chunks of 64
    const int SPLIT = kA0 >> 6;

    __half* stA = (__half*)smraw;        // [2][4096]
    __half* stB = stA + 2 * 4096;        // [2][3072]
    float* epGi = (float*)smraw;         // [64][50] (overlays dead stage bufs)
    float* epGh = epGi + 64 * 50;        // [64][50]

    float accA[6][4] = {};
    float accB[6][4] = {};

    // prologue: stage chunk 0 into buffer 0
    {
        #pragma unroll
        for (int i = 0; i < 4; i++) {
            int idx = tid + i * 128; int row = idx >> 3, c16 = idx & 7;
            int k = c16 * 8;
            const __half* s = (k < kA0) ? (A0 + (size_t)row * sA0 + k)
                                        : (A1 + (size_t)row * sA1 + (k - kA0));
            cp_async16(stA + row * 64 + ((c16 ^ (row & 7)) << 3), s);
        }
        #pragma unroll
        for (int i = 0; i < 3; i++) {
            int idx = tid + i * 128; int row = idx >> 3, c16 = idx & 7;
            size_t grow = (size_t)((row >> 4) * HID + j0 + (row & 15));
            cp_async16(stB + row * 64 + ((c16 ^ (row & 7)) << 3),
                       Bm + grow * Kdim + c16 * 8);
        }
        asm volatile("cp.async.commit_group;\n" ::: "memory");
    }

    for (int c = 0; c < NC; c++) {
        int pb = c & 1;
        if (c + 1 < NC) {
            int nb = pb ^ 1;
            int kbase = (c + 1) << 6;
            __half* dA = stA + nb * 4096;
            #pragma unroll
            for (int i = 0; i < 4; i++) {
                int idx = tid + i * 128; int row = idx >> 3, c16 = idx & 7;
                int k = kbase + c16 * 8;
                const __half* s = (k < kA0) ? (A0 + (size_t)row * sA0 + k)
                                            : (A1 + (size_t)row * sA1 + (k - kA0));
                cp_async16(dA + row * 64 + ((c16 ^ (row & 7)) << 3), s);
            }
            __half* dB = stB + nb * 3072;
            #pragma unroll
            for (int i = 0; i < 3; i++) {
                int idx = tid + i * 128; int row = idx >> 3, c16 = idx & 7;
                size_t grow = (size_t)((row >> 4) * HID + j0 + (row & 15));
                cp_async16(dB + row * 64 + ((c16 ^ (row & 7)) << 3),
                           Bm + grow * Kdim + kbase + c16 * 8);
            }
            asm volatile("cp.async.commit_group;\n" ::: "memory");
            asm volatile("cp.async.wait_group 1;\n" ::: "memory");
        } else {
            asm volatile("cp.async.wait_group 0;\n" ::: "memory");
        }
        __syncthreads();

        const __half* bA = stA + pb * 4096;
        const __half* bB = stB + pb * 3072;
        float (*acc)[4] = (c < SPLIT) ? accA : accB;
        #pragma unroll
        for (int ks = 0; ks < 4; ks++) {
            int arow = wid * 16 + (lane & 15);
            int ac16 = ks * 2 + (lane >> 4);
            uint32_t a0, a1, a2, a3;
            ldsm4(a0, a1, a2, a3, bA + arow * 64 + ((ac16 ^ (arow & 7)) << 3));
            #pragma unroll
            for (int ng = 0; ng < 3; ng++) {
                int brow = ng * 16 + (lane & 15);
                int bc16 = ks * 2 + (lane >> 4);
                uint32_t r0, r1, r2, r3;
                ldsm4(r0, r1, r2, r3, bB + brow * 64 + ((bc16 ^ (brow & 7)) << 3));
                mma_fp16(acc[2 * ng],     a0, a1, a2, a3, r0, r2);
                mma_fp16(acc[2 * ng + 1], a0, a1, a2, a3, r1, r3);
            }
        }
        __syncthreads();
    }

    // ---- epilogue: accumulators -> smem ----
    #pragma unroll
    for (int nt = 0; nt < 6; nt++) {
        int col = nt * 8 + (lane & 3) * 2;
        int m0 = wid * 16 + (lane >> 2);
        epGi[m0 * 50 + col]           = accA[nt][0];
        epGi[m0 * 50 + col + 1]       = accA[nt][1];
        epGi[(m0 + 8) * 50 + col]     = accA[nt][2];
        epGi[(m0 + 8) * 50 + col + 1] = accA[nt][3];
        epGh[m0 * 50 + col]           = accB[nt][0];
        epGh[m0 * 50 + col + 1]       = accB[nt][1];
        epGh[(m0 + 8) * 50 + col]     = accB[nt][2];
        epGh[(m0 + 8) * 50 + col + 1] = accB[nt][3];
    }
    __syncthreads();

    // ---- GRU gate math + state write ----
    #pragma unroll
    for (int it = 0; it < 8; it++) {
        int e = tid + it * 128;
        int m = e >> 4, u = e & 15;
        int j = j0 + u;
        float gir = epGi[m * 50 + u]       + b_ih[j];
        float giz = epGi[m * 50 + 16 + u]  + b_ih[HID + j];
        float gin = epGi[m * 50 + 32 + u]  + b_ih[2 * HID + j];
        float ghr = epGh[m * 50 + u]       + b_hh[j];
        float ghz = epGh[m * 50 + 16 + u]  + b_hh[HID + j];
        float ghn = epGh[m * 50 + 32 + u]  + b_hh[2 * HID + j];
        float r = 1.0f / (1.0f + __expf(-(gir + ghr)));
        float z = 1.0f / (1.0f + __expf(-(giz + ghz)));
        float n = tanhf(gin + r * ghn);
        float h = (1.0f - z) * n + z * h_old[m * HID + j];
        hnf[m * HID + j] = h;
        hnh[m * HID + j] = __float2half(h);
        if (hids) hids[(size_t)m * TSTEPS * HID + j] = h;  // dec_hids[n][t][:]
    }
}

// -------- wave kernel: L0(step w) on CTAs 0-63, L1(step w-1) on CTAs 64-127 --------
// L1(t) needs h0(t) [prev wave] and h1(t-1); L0(t+1) needs h0(t) [prev wave].
// Concurrent halves touch disjoint write buffers (parity-checked), so one kernel
// boundary per wave is the only ordering needed.
__global__ __launch_bounds__(128, 1) void k_wave(int w,
                                                 const float* __restrict__ bih0,
                                                 const float* __restrict__ bhh0,
                                                 const float* __restrict__ bih1,
                                                 const float* __restrict__ bhh1,
                                                 float* __restrict__ out) {
    __shared__ __align__(16) unsigned char smraw[28672];
    if (blockIdx.x < 64) {
        if (w < TSTEPS) step_body(0, w, blockIdx.x, bih0, bhh0, out, smraw);
    } else {
        if (w >= 1) step_body(1, w - 1, blockIdx.x - 64, bih1, bhh1, out, smraw);
    }
}

// -------- launcher (graph-capturable: kernel launches only) --------
extern "C" void kernel_launch(void* const* d_in, const int* in_sizes, int n_in,
                              void* d_out, int out_size) {
    const int*   tokens   = (const int*)d_in[0];
    const float* dec_init = (const float*)d_in[1];
    const float* emb      = (const float*)d_in[2];
    const float* Wih0     = (const float*)d_in[3];
    const float* Whh0     = (const float*)d_in[4];
    const float* bih0     = (const float*)d_in[5];
    const float* bhh0     = (const float*)d_in[6];
    const float* Wih1     = (const float*)d_in[7];
    const float* Whh1     = (const float*)d_in[8];
    const float* bih1     = (const float*)d_in[9];
    const float* bhh1     = (const float*)d_in[10];
    float* out = (float*)d_out;

    k_init<<<64, 256>>>(dec_init);
    k_pack<<<512, 256>>>(Wih0, Whh0, Wih1, Whh1);
    k_embed<<<TSTEPS * NB, 128>>>(tokens, emb);

    for (int w = 0; w <= TSTEPS; w++)
        k_wave<<<128, 128>>>(w, bih0, bhh0, bih1, bhh1, out);

    k_final<<<64, 256>>>(out);
}

// round 15
// speedup vs baseline: 1.6167x; 1.6167x over previous
#include <cuda_runtime.h>
#include <cuda_fp16.h>
#include <cstdint>

#define NB     64
#define EMB    512
#define HID    1024
#define LSEQ   512
#define TSTEPS 511

#define STAGE_BYTES 14336          // A 64x64 half (8192B) + B 48x64 half (6144B)
#define NSTAGE      3

// -------- device global scratch (allocation-free rule) --------
__device__ __align__(16) __half g_X[(size_t)TSTEPS * NB * EMB]; // [t][n][k]
__device__ __align__(16) __half g_B0[3072 * 1536];              // row j: [Wih0 | Whh0]
__device__ __align__(16) __half g_B1[3072 * 2048];              // row j: [Wih1 | Whh1]
__device__ __align__(16) float  g_h0f[2][NB * HID];
__device__ __align__(16) float  g_h1f[2][NB * HID];
__device__ __align__(16) __half g_h0h[2][NB * HID];
__device__ __align__(16) __half g_h1h[2][NB * HID];

// -------- PTX helpers --------
__device__ __forceinline__ void cp_async16(void* s, const void* g) {
    uint32_t sa = (uint32_t)__cvta_generic_to_shared(s);
    asm volatile("cp.async.cg.shared.global [%0], [%1], 16;\n" :: "r"(sa), "l"(g));
}
__device__ __forceinline__ void ldsm4(uint32_t& r0, uint32_t& r1, uint32_t& r2, uint32_t& r3,
                                      const void* p) {
    uint32_t a = (uint32_t)__cvta_generic_to_shared(p);
    asm volatile("ldmatrix.sync.aligned.m8n8.x4.shared.b16 {%0,%1,%2,%3}, [%4];\n"
                 : "=r"(r0), "=r"(r1), "=r"(r2), "=r"(r3) : "r"(a));
}
__device__ __forceinline__ void mma_fp16(float (&d)[4], uint32_t a0, uint32_t a1, uint32_t a2,
                                         uint32_t a3, uint32_t b0, uint32_t b1) {
    asm volatile(
        "mma.sync.aligned.m16n8k16.row.col.f32.f16.f16.f32 "
        "{%0,%1,%2,%3},{%4,%5,%6,%7},{%8,%9},{%0,%1,%2,%3};\n"
        : "+f"(d[0]), "+f"(d[1]), "+f"(d[2]), "+f"(d[3])
        : "r"(a0), "r"(a1), "r"(a2), "r"(a3), "r"(b0), "r"(b1));
}

// -------- one-time (per replay) prep kernels --------
__global__ void k_init(const float* __restrict__ dec_init) {
    for (int i = blockIdx.x * blockDim.x + threadIdx.x; i < NB * HID;
         i += gridDim.x * blockDim.x) {
        float v0 = dec_init[i];
        float v1 = dec_init[NB * HID + i];
        g_h0f[0][i] = v0; g_h0h[0][i] = __float2half(v0);
        g_h1f[0][i] = v1; g_h1h[0][i] = __float2half(v1);
    }
}

__global__ void k_pack(const float* __restrict__ Wih0, const float* __restrict__ Whh0,
                       const float* __restrict__ Wih1, const float* __restrict__ Whh1) {
    const int N0 = 3072 * 1536;
    const int N1 = 3072 * 2048;
    for (int i = blockIdx.x * blockDim.x + threadIdx.x; i < N0 + N1;
         i += gridDim.x * blockDim.x) {
        if (i < N0) {
            int j = i / 1536, k = i % 1536;
            float v = (k < 512) ? Wih0[(size_t)j * 512 + k] : Whh0[(size_t)j * 1024 + (k - 512)];
            g_B0[i] = __float2half(v);
        } else {
            int ii = i - N0;
            int j = ii >> 11, k = ii & 2047;
            float v = (k < 1024) ? Wih1[(size_t)j * 1024 + k] : Whh1[(size_t)j * 1024 + (k - 1024)];
            g_B1[ii] = __float2half(v);
        }
    }
}

__global__ void k_embed(const int* __restrict__ tokens, const float* __restrict__ emb) {
    int tn = blockIdx.x;          // t*64 + n
    int t = tn >> 6, n = tn & 63;
    int tok = tokens[n * LSEQ + t];      // tokens[:, :-1] -> col t < 511
    const float* src = emb + (size_t)tok * EMB;
    __half* dst = g_X + (size_t)tn * EMB;
    for (int k = threadIdx.x; k < EMB; k += blockDim.x)
        dst[k] = __float2half(src[k]);
}

__global__ void k_final(float* __restrict__ out) {
    size_t base = (size_t)NB * TSTEPS * HID;
    for (int i = blockIdx.x * blockDim.x + threadIdx.x; i < NB * HID;
         i += gridDim.x * blockDim.x) {
        out[base + i] = g_h0f[1][i];                // 511 steps -> final parity buffer = 1
        out[base + NB * HID + i] = g_h1f[1][i];
    }
}

// -------- stage loader: chunk c -> ring slot --------
__device__ __forceinline__ void load_chunk(int c, int slot, int tid,
                                           const __half* A0, int sA0, int kA0,
                                           const __half* A1, int sA1,
                                           const __half* Bm, int Kdim, int j0,
                                           unsigned char* smraw) {
    __half* dA = (__half*)(smraw + slot * STAGE_BYTES);
    __half* dB = dA + 4096;
    const int kbase = c << 6;
    // A: 64 rows x 64 cols = 512 x 16B
    {
        int idx = tid; int row = idx >> 3, c16 = idx & 7;
        int k = kbase + c16 * 8;
        const __half* s = (k < kA0) ? (A0 + (size_t)row * sA0 + k)
                                    : (A1 + (size_t)row * sA1 + (k - kA0));
        cp_async16(dA + row * 64 + ((c16 ^ (row & 7)) << 3), s);
    }
    if (tid < 128) {
        int idx = tid + 384; int row = idx >> 3, c16 = idx & 7;
        int k = kbase + c16 * 8;
        const __half* s = (k < kA0) ? (A0 + (size_t)row * sA0 + k)
                                    : (A1 + (size_t)row * sA1 + (k - kA0));
        cp_async16(dA + row * 64 + ((c16 ^ (row & 7)) << 3), s);
    }
    // B: 48 rows x 64 cols = 384 x 16B
    {
        int idx = tid; int row = idx >> 3, c16 = idx & 7;
        size_t grow = (size_t)((row >> 4) * HID + j0 + (row & 15));
        cp_async16(dB + row * 64 + ((c16 ^ (row & 7)) << 3),
                   Bm + grow * Kdim + kbase + c16 * 8);
    }
    asm volatile("cp.async.commit_group;\n" ::: "memory");
}

// -------- fused GEMM + GRU gate body (one layer, one step, one 16-unit tile) --------
// 384 threads = 12 warps = 4 M-tiles x 3 N16-tiles; each warp: 8 mma per K chunk.
// GEMM: M=64, N=48 (3 gates x 16 units), K fused [input | hidden]; accA = gi, accB = gh,
// selected by K-chunk (n = tanh(gi_n + r * gh_n) needs them separate).
__device__ __forceinline__ void step_body(int layer, int t, int jblk,
                                          const float* __restrict__ b_ih,
                                          const float* __restrict__ b_hh,
                                          float* __restrict__ out,
                                          unsigned char* smraw) {
    const int tid = threadIdx.x;
    const int wid = tid >> 5;
    const int lane = tid & 31;
    const int wm = wid & 3;      // M tile 0-3
    const int ng = wid >> 2;     // N16 tile 0-2
    const int j0 = jblk * 16;
    const int p = t & 1;

    const __half *A0, *A1, *Bm;
    const float* h_old;
    float* hnf;
    __half* hnh;
    float* hids;
    int sA0, kA0, sA1, Kdim;
    if (layer == 0) {
        A0 = g_X + (size_t)t * NB * EMB; sA0 = EMB; kA0 = EMB;
        A1 = g_h0h[p]; sA1 = HID;
        Bm = g_B0; Kdim = 1536;
        h_old = g_h0f[p]; hnf = g_h0f[p ^ 1]; hnh = g_h0h[p ^ 1]; hids = nullptr;
    } else {
        A0 = g_h0h[p ^ 1]; sA0 = HID; kA0 = HID;
        A1 = g_h1h[p]; sA1 = HID;
        Bm = g_B1; Kdim = 2048;
        h_old = g_h1f[p]; hnf = g_h1f[p ^ 1]; hnh = g_h1h[p ^ 1];
        hids = out + (size_t)t * HID;
    }
    const int NC = Kdim >> 6;     // 24 (L0) or 32 (L1)
    const int SPLIT = kA0 >> 6;

    float* epGi = (float*)smraw;          // [64][50] overlays dead stage bufs post-loop
    float* epGh = epGi + 64 * 50;

    float accA[2][4] = {};
    float accB[2][4] = {};

    // prologue: stage chunks 0,1 into slots 0,1
    load_chunk(0, 0, tid, A0, sA0, kA0, A1, sA1, Bm, Kdim, j0, smraw);
    load_chunk(1, 1, tid, A0, sA0, kA0, A1, sA1, Bm, Kdim, j0, smraw);

    int slot = 0;
    for (int c = 0; c < NC; c++) {
        if (c + 1 < NC) asm volatile("cp.async.wait_group 1;\n" ::: "memory");
        else            asm volatile("cp.async.wait_group 0;\n" ::: "memory");
        __syncthreads();   // chunk c visible to all; all warps done with chunk c-1

        const __half* bA = (const __half*)(smraw + slot * STAGE_BYTES);
        const __half* bB = bA + 4096;
        float (*acc)[4] = (c < SPLIT) ? accA : accB;
        const int arow = wm * 16 + (lane & 15);
        const int brow = ng * 16 + (lane & 15);
        #pragma unroll
        for (int ks = 0; ks < 4; ks++) {
            int c16 = ks * 2 + (lane >> 4);
            uint32_t a0, a1, a2, a3;
            ldsm4(a0, a1, a2, a3, bA + arow * 64 + ((c16 ^ (arow & 7)) << 3));
            uint32_t r0, r1, r2, r3;
            ldsm4(r0, r1, r2, r3, bB + brow * 64 + ((c16 ^ (brow & 7)) << 3));
            mma_fp16(acc[0], a0, a1, a2, a3, r0, r2);
            mma_fp16(acc[1], a0, a1, a2, a3, r1, r3);
        }

        if (c + 2 < NC) {
            int ns = slot + 2; if (ns >= NSTAGE) ns -= NSTAGE;
            load_chunk(c + 2, ns, tid, A0, sA0, kA0, A1, sA1, Bm, Kdim, j0, smraw);
        }
        if (++slot == NSTAGE) slot = 0;
    }
    __syncthreads();   // all compute done before epilogue overlays stage buffers

    // ---- epilogue: accumulators -> smem (disjoint (wm, ng) slices) ----
    #pragma unroll
    for (int nt = 0; nt < 2; nt++) {
        int col = ng * 16 + nt * 8 + (lane & 3) * 2;
        int m0 = wm * 16 + (lane >> 2);
        epGi[m0 * 50 + col]           = accA[nt][0];
        epGi[m0 * 50 + col + 1]       = accA[nt][1];
        epGi[(m0 + 8) * 50 + col]     = accA[nt][2];
        epGi[(m0 + 8) * 50 + col + 1] = accA[nt][3];
        epGh[m0 * 50 + col]           = accB[nt][0];
        epGh[m0 * 50 + col + 1]       = accB[nt][1];
        epGh[(m0 + 8) * 50 + col]     = accB[nt][2];
        epGh[(m0 + 8) * 50 + col + 1] = accB[nt][3];
    }
    __syncthreads();

    // ---- GRU gate math + state write (1024 elems over 384 threads) ----
    #pragma unroll
    for (int it = 0; it < 3; it++) {
        int e = tid + it * 384;
        if (e < 1024) {
            int bm = e >> 4, u = e & 15;
            int j = j0 + u;
            float gir = epGi[bm * 50 + u]       + b_ih[j];
            float giz = epGi[bm * 50 + 16 + u]  + b_ih[HID + j];
            float gin = epGi[bm * 50 + 32 + u]  + b_ih[2 * HID + j];
            float ghr = epGh[bm * 50 + u]       + b_hh[j];
            float ghz = epGh[bm * 50 + 16 + u]  + b_hh[HID + j];
            float ghn = epGh[bm * 50 + 32 + u]  + b_hh[2 * HID + j];
            float r = 1.0f / (1.0f + __expf(-(gir + ghr)));
            float z = 1.0f / (1.0f + __expf(-(giz + ghz)));
            float n = tanhf(gin + r * ghn);
            float h = (1.0f - z) * n + z * h_old[bm * HID + j];
            hnf[bm * HID + j] = h;
            hnh[bm * HID + j] = __float2half(h);
            if (hids) hids[(size_t)bm * TSTEPS * HID + j] = h;  // dec_hids[n][t][:]
        }
    }
}

// -------- wave kernel: L0(step w) on CTAs 0-63, L1(step w-1) on CTAs 64-127 --------
// L1(t) needs h0(t) [prev wave] and h1(t-1); L0(t+1) needs h0(t) [prev wave].
// Concurrent halves write disjoint parity buffers; the kernel boundary is the only
// ordering needed.
__global__ __launch_bounds__(384, 1) void k_wave(int w,
                                                 const float* __restrict__ bih0,
                                                 const float* __restrict__ bhh0,
                                                 const float* __restrict__ bih1,
                                                 const float* __restrict__ bhh1,
                                                 float* __restrict__ out) {
    __shared__ __align__(16) unsigned char smraw[NSTAGE * STAGE_BYTES];
    if (blockIdx.x < 64) {
        if (w < TSTEPS) step_body(0, w, blockIdx.x, bih0, bhh0, out, smraw);
    } else {
        if (w >= 1) step_body(1, w - 1, blockIdx.x - 64, bih1, bhh1, out, smraw);
    }
}

// -------- launcher (graph-capturable: kernel launches only) --------
extern "C" void kernel_launch(void* const* d_in, const int* in_sizes, int n_in,
                              void* d_out, int out_size) {
    const int*   tokens   = (const int*)d_in[0];
    const float* dec_init = (const float*)d_in[1];
    const float* emb      = (const float*)d_in[2];
    const float* Wih0     = (const float*)d_in[3];
    const float* Whh0     = (const float*)d_in[4];
    const float* bih0     = (const float*)d_in[5];
    const float* bhh0     = (const float*)d_in[6];
    const float* Wih1     = (const float*)d_in[7];
    const float* Whh1     = (const float*)d_in[8];
    const float* bih1     = (const float*)d_in[9];
    const float* bhh1     = (const float*)d_in[10];
    float* out = (float*)d_out;

    k_init<<<64, 256>>>(dec_init);
    k_pack<<<512, 256>>>(Wih0, Whh0, Wih1, Whh1);
    k_embed<<<TSTEPS * NB, 128>>>(tokens, emb);

    for (int w = 0; w <= TSTEPS; w++)
        k_wave<<<128, 384>>>(w, bih0, bhh0, bih1, bhh1, out);

    k_final<<<64, 256>>>(out);
}